// round 12
// baseline (speedup 1.0000x reference)
#include <cuda_runtime.h>
#include <cuda_bf16.h>
#include <cstdint>

// velocity = MLP(concat(zone_embedding, person_attrs, time_vec)).
// GCN layers are dead code w.r.t. the output; person/time layer-1
// contributions are row-constant, folded into g_c1 by the prep kernel.
//
// R12 = R10 kernel (bf16 3-term-split mma.m16n8k16, register-chained layers,
// global pre-packed B-fragments -> L1-hit LDG) + PDL: velo is launched with
// programmaticStreamSerializationAllowed and overlaps its prep-independent
// z-loads with prep's execution, calling cudaGridDependencySynchronize()
// only before consuming fragments. launch_bounds(128,4) caps regs at 128
// for 4 blocks/SM (waves 1.76 -> 1.32).

#define HID 32
#define H1  64
#define TPB 128            // 4 warps, 32 rows/warp, 128 rows/block

typedef uint32_t u32;

__device__ __align__(16) float g_c1[H1];     // folded layer-1 bias
__device__ uint4 g_W1f[16 * 32];             // (nt8*2 + kt2) x lane
__device__ uint4 g_W2f[16 * 32];             // (nt4*4 + kt4) x lane
__device__ uint4 g_W3f[ 8 * 32];             // (nt4*2 + kt2) x lane

// pack pair (x0 -> low half, x1 -> high half) into bf16x2 hi, residual lo.
__device__ __forceinline__ void split2(float x0, float x1, u32& hi, u32& lo) {
    asm("cvt.rn.bf16x2.f32 %0, %1, %2;" : "=r"(hi) : "f"(x1), "f"(x0));
    float h0 = __uint_as_float(hi << 16);
    float h1 = __uint_as_float(hi & 0xffff0000u);
    float r0 = x0 - h0;
    float r1 = x1 - h1;
    asm("cvt.rn.bf16x2.f32 %0, %1, %2;" : "=r"(lo) : "f"(r1), "f"(r0));
}

__device__ __forceinline__ void mma_bf16(float d[4], const u32 a[4], u32 b0, u32 b1) {
    asm("mma.sync.aligned.m16n8k16.row.col.f32.bf16.bf16.f32 "
        "{%0,%1,%2,%3}, {%4,%5,%6,%7}, {%8,%9}, {%0,%1,%2,%3};"
        : "+f"(d[0]), "+f"(d[1]), "+f"(d[2]), "+f"(d[3])
        : "r"(a[0]), "r"(a[1]), "r"(a[2]), "r"(a[3]), "r"(b0), "r"(b1));
}

// ---------------------------------------------------------------------------
// Prep: fold c1, pack all weight B-fragments (hi/lo). One block, 256 threads.
// Triggers the dependent velo launch immediately on entry.
// ---------------------------------------------------------------------------
__global__ void prep_kernel(const float* __restrict__ t,
                            const float* __restrict__ pa,
                            const float* __restrict__ Wt1, const float* __restrict__ bt1,
                            const float* __restrict__ Wt2, const float* __restrict__ bt2,
                            const float* __restrict__ Wd1, const float* __restrict__ bd1,
                            const float* __restrict__ Wd2, const float* __restrict__ Wd3)
{
    cudaTriggerProgrammaticLaunchCompletion();   // let velo's grid launch now

    __shared__ float u[16];
    __shared__ float tv[16];
    const int tid = threadIdx.x;

    if (tid < 16) u[tid] = fmaxf(fmaf(t[0], Wt1[tid], bt1[tid]), 0.0f);
    __syncthreads();
    if (tid < 16) {
        float a = bt2[tid];
        #pragma unroll
        for (int i = 0; i < 16; i++) a = fmaf(u[i], Wt2[i * 16 + tid], a);
        tv[tid] = a;
    }
    __syncthreads();
    if (tid < H1) {
        float a = bd1[tid];
        #pragma unroll
        for (int p = 0; p < 8; p++)  a = fmaf(pa[p], Wd1[(HID + p) * H1 + tid], a);
        #pragma unroll
        for (int i = 0; i < 16; i++) a = fmaf(tv[i], Wd1[(HID + 8 + i) * H1 + tid], a);
        g_c1[tid] = a;
    }

    for (int idx = tid; idx < 1280; idx += 256) {
        const float* W;
        int stride, nt, kt, lane;
        uint4* dst;
        int slot;
        if (idx < 512) {                 // W1: zone part of Wd1 [32 x 64]
            int s = idx;        lane = s & 31; int ntkt = s >> 5;
            nt = ntkt >> 1; kt = ntkt & 1;
            W = Wd1; stride = 64; dst = g_W1f; slot = s;
        } else if (idx < 1024) {         // W2 [64 x 32]
            int s = idx - 512;  lane = s & 31; int ntkt = s >> 5;
            nt = ntkt >> 2; kt = ntkt & 3;
            W = Wd2; stride = 32; dst = g_W2f; slot = s;
        } else {                         // W3 [32 x 32]
            int s = idx - 1024; lane = s & 31; int ntkt = s >> 5;
            nt = ntkt >> 1; kt = ntkt & 1;
            W = Wd3; stride = 32; dst = g_W3f; slot = s;
        }
        int g = lane >> 2, tt = lane & 3;
        int col  = 8 * nt + g;
        int krow = 16 * kt + 2 * tt;
        float w00 = W[(krow    ) * stride + col];
        float w01 = W[(krow + 1) * stride + col];
        float w10 = W[(krow + 8) * stride + col];
        float w11 = W[(krow + 9) * stride + col];
        uint4 f;
        split2(w00, w01, f.x, f.z);
        split2(w10, w11, f.y, f.w);
        dst[slot] = f;
    }
}

// ---------------------------------------------------------------------------
// Main: 4 warps/block, 32 rows/warp (2 m16 tiles, both live per layer).
// Launched with PDL: z-loads happen before cudaGridDependencySynchronize().
// ---------------------------------------------------------------------------
__global__ void __launch_bounds__(TPB, 4)
velo_kernel(const float* __restrict__ emb,
            const float* __restrict__ bd2, const float* __restrict__ bd3,
            float* __restrict__ out, int nrows)
{
    const int warp = threadIdx.x >> 5;
    const int lane = threadIdx.x & 31;
    const int g = lane >> 2, t = lane & 3;
    const int row_base = blockIdx.x * 128 + warp * 32;

    const float2 zero2 = make_float2(0.0f, 0.0f);
    int ra[2], rb[2];
    #pragma unroll
    for (int mt = 0; mt < 2; ++mt) { ra[mt] = row_base + 16 * mt + g; rb[mt] = ra[mt] + 8; }

    // ---- prep-independent: load z and build A1 fragments ----
    u32 A1h[2][2][4], A1l[2][2][4];
    if (row_base < nrows) {
        #pragma unroll
        for (int mt = 0; mt < 2; ++mt) {
            #pragma unroll
            for (int kt = 0; kt < 2; ++kt) {
                float2 p0 = (ra[mt] < nrows) ? *reinterpret_cast<const float2*>(emb + (size_t)ra[mt] * 32 + 16 * kt + 2 * t)     : zero2;
                float2 p1 = (rb[mt] < nrows) ? *reinterpret_cast<const float2*>(emb + (size_t)rb[mt] * 32 + 16 * kt + 2 * t)     : zero2;
                float2 p2 = (ra[mt] < nrows) ? *reinterpret_cast<const float2*>(emb + (size_t)ra[mt] * 32 + 16 * kt + 8 + 2 * t) : zero2;
                float2 p3 = (rb[mt] < nrows) ? *reinterpret_cast<const float2*>(emb + (size_t)rb[mt] * 32 + 16 * kt + 8 + 2 * t) : zero2;
                split2(p0.x, p0.y, A1h[mt][kt][0], A1l[mt][kt][0]);
                split2(p1.x, p1.y, A1h[mt][kt][1], A1l[mt][kt][1]);
                split2(p2.x, p2.y, A1h[mt][kt][2], A1l[mt][kt][2]);
                split2(p3.x, p3.y, A1h[mt][kt][3], A1l[mt][kt][3]);
            }
        }
    }

    // ---- wait for prep's fragment/bias writes to be visible ----
    cudaGridDependencySynchronize();

    if (row_base >= nrows) return;

    // ---- layer1 (K=32, N=64): nt-outer, both m-tiles per B fragment ----
    u32 A2h[2][4][4], A2l[2][4][4];
    #pragma unroll
    for (int nt = 0; nt < 8; ++nt) {
        float d[2][4] = {{0.f,0.f,0.f,0.f},{0.f,0.f,0.f,0.f}};
        #pragma unroll
        for (int kt = 0; kt < 2; ++kt) {
            uint4 B = g_W1f[(nt * 2 + kt) * 32 + lane];
            #pragma unroll
            for (int mt = 0; mt < 2; ++mt) {
                mma_bf16(d[mt], A1h[mt][kt], B.x, B.y);
                mma_bf16(d[mt], A1h[mt][kt], B.z, B.w);
                mma_bf16(d[mt], A1l[mt][kt], B.x, B.y);
            }
        }
        float2 cb = *reinterpret_cast<const float2*>(g_c1 + 8 * nt + 2 * t);
        int kt2 = nt >> 1, off = (nt & 1) * 2;
        #pragma unroll
        for (int mt = 0; mt < 2; ++mt) {
            float h0 = fmaxf(d[mt][0] + cb.x, 0.0f);
            float h1 = fmaxf(d[mt][1] + cb.y, 0.0f);
            float h2 = fmaxf(d[mt][2] + cb.x, 0.0f);
            float h3 = fmaxf(d[mt][3] + cb.y, 0.0f);
            split2(h0, h1, A2h[mt][kt2][off],     A2l[mt][kt2][off]);
            split2(h2, h3, A2h[mt][kt2][off + 1], A2l[mt][kt2][off + 1]);
        }
    }

    // ---- layer2 (K=64, N=32) ----
    u32 A3h[2][2][4], A3l[2][2][4];
    #pragma unroll
    for (int nt = 0; nt < 4; ++nt) {
        float d[2][4] = {{0.f,0.f,0.f,0.f},{0.f,0.f,0.f,0.f}};
        #pragma unroll
        for (int kt = 0; kt < 4; ++kt) {
            uint4 B = g_W2f[(nt * 4 + kt) * 32 + lane];
            #pragma unroll
            for (int mt = 0; mt < 2; ++mt) {
                mma_bf16(d[mt], A2h[mt][kt], B.x, B.y);
                mma_bf16(d[mt], A2h[mt][kt], B.z, B.w);
                mma_bf16(d[mt], A2l[mt][kt], B.x, B.y);
            }
        }
        float2 bb = *reinterpret_cast<const float2*>(bd2 + 8 * nt + 2 * t);
        int kt3 = nt >> 1, off = (nt & 1) * 2;
        #pragma unroll
        for (int mt = 0; mt < 2; ++mt) {
            float h0 = fmaxf(d[mt][0] + bb.x, 0.0f);
            float h1 = fmaxf(d[mt][1] + bb.y, 0.0f);
            float h2 = fmaxf(d[mt][2] + bb.x, 0.0f);
            float h3 = fmaxf(d[mt][3] + bb.y, 0.0f);
            split2(h0, h1, A3h[mt][kt3][off],     A3l[mt][kt3][off]);
            split2(h2, h3, A3h[mt][kt3][off + 1], A3l[mt][kt3][off + 1]);
        }
    }

    // ---- layer3 (K=32, N=32) + bias, store ----
    #pragma unroll
    for (int nt = 0; nt < 4; ++nt) {
        float d[2][4] = {{0.f,0.f,0.f,0.f},{0.f,0.f,0.f,0.f}};
        #pragma unroll
        for (int kt = 0; kt < 2; ++kt) {
            uint4 B = g_W3f[(nt * 2 + kt) * 32 + lane];
            #pragma unroll
            for (int mt = 0; mt < 2; ++mt) {
                mma_bf16(d[mt], A3h[mt][kt], B.x, B.y);
                mma_bf16(d[mt], A3h[mt][kt], B.z, B.w);
                mma_bf16(d[mt], A3l[mt][kt], B.x, B.y);
            }
        }
        float2 b3 = *reinterpret_cast<const float2*>(bd3 + 8 * nt + 2 * t);
        #pragma unroll
        for (int mt = 0; mt < 2; ++mt) {
            if (ra[mt] < nrows)
                *reinterpret_cast<float2*>(out + (size_t)ra[mt] * 32 + 8 * nt + 2 * t) = make_float2(d[mt][0] + b3.x, d[mt][1] + b3.y);
            if (rb[mt] < nrows)
                *reinterpret_cast<float2*>(out + (size_t)rb[mt] * 32 + 8 * nt + 2 * t) = make_float2(d[mt][2] + b3.x, d[mt][3] + b3.y);
        }
    }
}

extern "C" void kernel_launch(void* const* d_in, const int* in_sizes, int n_in,
                              void* d_out, int out_size)
{
    const float* t   = (const float*)d_in[0];
    const float* emb = (const float*)d_in[1];
    const float* pa  = (const float*)d_in[3];
    const float* Wt1 = (const float*)d_in[9];
    const float* bt1 = (const float*)d_in[10];
    const float* Wt2 = (const float*)d_in[11];
    const float* bt2 = (const float*)d_in[12];
    const float* Wd1 = (const float*)d_in[13];
    const float* bd1 = (const float*)d_in[14];
    const float* Wd2 = (const float*)d_in[15];
    const float* bd2 = (const float*)d_in[16];
    const float* Wd3 = (const float*)d_in[17];
    const float* bd3 = (const float*)d_in[18];
    float* out = (float*)d_out;

    const int nrows = in_sizes[1] / HID;

    prep_kernel<<<1, 256>>>(t, pa, Wt1, bt1, Wt2, bt2, Wd1, bd1, Wd2, Wd3);

    // PDL launch: velo may begin before prep completes; it gridsyncs before
    // consuming prep's outputs.
    cudaLaunchConfig_t cfg = {};
    cfg.gridDim  = dim3((nrows + 127) / 128, 1, 1);
    cfg.blockDim = dim3(TPB, 1, 1);
    cudaLaunchAttribute attr[1];
    attr[0].id = cudaLaunchAttributeProgrammaticStreamSerialization;
    attr[0].val.programmaticStreamSerializationAllowed = 1;
    cfg.attrs = attr;
    cfg.numAttrs = 1;
    cudaLaunchKernelEx(&cfg, velo_kernel, emb, bd2, bd3, out, nrows);
}